// round 5
// baseline (speedup 1.0000x reference)
#include <cuda_runtime.h>
#include <cuda_bf16.h>
#include <cstdint>

#define BB 256
#define SS 512
#define DD 1024
#define TT 17
#define EST 20   // padded eem row stride (16B-aligned rows)

// ---------------- device scratch (no allocations allowed) ----------------
__device__ float g_eem[(size_t)BB * SS * EST];  // exp(em - rowmax), 10.5 MB
__device__ float g_part_score[512];             // per-block numerator partials
__device__ float g_part_msum[512];              // per-block sum of masked row-maxes
__device__ int   g_part_mcnt[512];              // per-block mask counts
__device__ float g_denom[BB];                   // log partition minus msum offset

__device__ __forceinline__ void fma2(unsigned long long &acc,
                                     unsigned long long a,
                                     unsigned long long b) {
    asm("fma.rn.f32x2 %0, %1, %2, %0;" : "+l"(acc) : "l"(a), "l"(b));
}

// ============================================================
// Kernel 1: emissions GEMM + eem/rowmax + numerator partials
//   512 blocks x 128 threads; block = 256 rows (half batch), R=2 rows/thread.
//   data staged via smem tiles (coalesced LDG, swizzled STS/LDS).
// ============================================================
__global__ void __launch_bounds__(128, 2)
emis_kernel(const float* __restrict__ data, const int* __restrict__ labels,
            const int* __restrict__ mask, const float* __restrict__ W,
            const float* __restrict__ bias, const float* __restrict__ start,
            const float* __restrict__ trans)
{
    extern __shared__ float smem[];
    float* sW = smem;            // 17*1024 floats (68 KB)
    float* sD = smem + TT * DD;  // 256 rows * 32 floats (32 KB)
    float* red = sD + 256 * 32;  // reduction tail

    const int tid = threadIdx.x;
    const int blk = blockIdx.x;              // half-batch index
    const int row_base = blk * 256;          // global row of block's row 0

    // cooperative load of W [T, D] into shared (float4)
    const float4* W4 = reinterpret_cast<const float4*>(W);
    float4* sW4 = reinterpret_cast<float4*>(sW);
    #pragma unroll 2
    for (int i = tid; i < TT * DD / 4; i += 128) sW4[i] = __ldg(W4 + i);

    const float4* dq = reinterpret_cast<const float4*>(data);
    // staging geometry: idx = tid + 128*i -> row = (tid>>3)+16*i, q = tid&7
    const int rb = tid >> 3;
    const int qq = tid & 7;
    const long gbase = (long)(row_base + rb) * 256 + qq;   // float4 units
    const int qs = (qq ^ (rb & 7)) << 2;                   // swizzled quad offset (floats)
    const int sbase = rb * 32 + qs;

    // prefetch tile 0
    float4 buf[16];
    #pragma unroll
    for (int i = 0; i < 16; i++) buf[i] = __ldg(dq + gbase + (long)i * 4096);

    __syncthreads();   // W ready, sD free

    unsigned long long acc[2][TT];
    #pragma unroll
    for (int r = 0; r < 2; r++)
        #pragma unroll
        for (int t = 0; t < TT; t++) acc[r][t] = 0ull;

    const int r0 = tid, r1 = tid + 128;
    const int sw0 = (r0 & 7), sw1 = (r1 & 7);
    const ulonglong2* sWv = reinterpret_cast<const ulonglong2*>(sW);

    for (int tt = 0; tt < 32; tt++) {
        // store staged regs into smem (swizzled)
        #pragma unroll
        for (int i = 0; i < 16; i++)
            *reinterpret_cast<float4*>(sD + sbase + i * 512) = buf[i];
        __syncthreads();

        // prefetch next tile
        if (tt < 31) {
            #pragma unroll
            for (int i = 0; i < 16; i++)
                buf[i] = __ldg(dq + gbase + (tt + 1) * 8 + (long)i * 4096);
        }

        // compute 8 k-quads of this tile
        #pragma unroll
        for (int kk = 0; kk < 8; kk++) {
            float4 d0 = *reinterpret_cast<const float4*>(sD + r0 * 32 + ((kk ^ sw0) << 2));
            float4 d1 = *reinterpret_cast<const float4*>(sD + r1 * 32 + ((kk ^ sw1) << 2));
            unsigned long long d0x = *reinterpret_cast<unsigned long long*>(&d0.x);
            unsigned long long d0y = *reinterpret_cast<unsigned long long*>(&d0.z);
            unsigned long long d1x = *reinterpret_cast<unsigned long long*>(&d1.x);
            unsigned long long d1y = *reinterpret_cast<unsigned long long*>(&d1.z);
            #pragma unroll
            for (int t = 0; t < TT; t++) {
                ulonglong2 w = sWv[t * 256 + tt * 8 + kk];
                fma2(acc[0][t], d0x, w.x);
                fma2(acc[0][t], d0y, w.y);
                fma2(acc[1][t], d1x, w.x);
                fma2(acc[1][t], d1y, w.y);
            }
        }
        __syncthreads();   // all reads done before next STS
    }

    // ---- epilogue: per-row max/exp/store + numerator accumulation ----
    float contrib = 0.0f, msum_t = 0.0f;
    int mcnt_t = 0;

    #pragma unroll
    for (int r = 0; r < 2; r++) {
        int lrow = tid + r * 128;          // 0..255 within block
        int row  = row_base + lrow;        // global row
        int s    = row & (SS - 1);

        float emv[TT];
        float m = -1e30f;
        #pragma unroll
        for (int t = 0; t < TT; t++) {
            float lo = __uint_as_float((unsigned)(acc[r][t] & 0xffffffffull));
            float hi = __uint_as_float((unsigned)(acc[r][t] >> 32));
            emv[t] = lo + hi + __ldg(bias + t);
            m = fmaxf(m, emv[t]);
        }

        float e[TT];
        #pragma unroll
        for (int t = 0; t < TT; t++) e[t] = __expf(emv[t] - m);

        float4* o4 = reinterpret_cast<float4*>(g_eem + (size_t)row * EST);
        o4[0] = make_float4(e[0],  e[1],  e[2],  e[3]);
        o4[1] = make_float4(e[4],  e[5],  e[6],  e[7]);
        o4[2] = make_float4(e[8],  e[9],  e[10], e[11]);
        o4[3] = make_float4(e[12], e[13], e[14], e[15]);
        o4[4] = make_float4(e[16], 0.0f,  0.0f,  0.0f);

        int lab = __ldg(labels + row);
        float em_lab = 0.0f;
        #pragma unroll
        for (int t = 0; t < TT; t++) em_lab = (lab == t) ? emv[t] : em_lab;

        float mk = (__ldg(mask + row) != 0) ? 1.0f : 0.0f;
        if (s == 0) {
            contrib += __ldg(start + lab) + em_lab;   // always included
        } else {
            int prev = __ldg(labels + row - 1);
            contrib += mk * (__ldg(trans + prev * TT + lab) + em_lab);
        }
        msum_t += mk * m;
        mcnt_t += (mk > 0.0f) ? 1 : 0;
    }

    // ---- block reduction (deterministic, no atomics); 4 warps ----
    const unsigned FULL = 0xffffffffu;
    #pragma unroll
    for (int off = 16; off; off >>= 1) {
        contrib += __shfl_xor_sync(FULL, contrib, off);
        msum_t  += __shfl_xor_sync(FULL, msum_t, off);
        mcnt_t  += __shfl_xor_sync(FULL, mcnt_t, off);
    }
    int wid = tid >> 5;
    if ((tid & 31) == 0) {
        red[wid]     = contrib;
        red[4 + wid] = msum_t;
        reinterpret_cast<int*>(red)[8 + wid] = mcnt_t;
    }
    __syncthreads();
    if (tid == 0) {
        float sc = 0.0f, sm = 0.0f; int cn = 0;
        #pragma unroll
        for (int w = 0; w < 4; w++) {
            sc += red[w];
            sm += red[4 + w];
            cn += reinterpret_cast<int*>(red)[8 + w];
        }
        g_part_score[blk] = sc;
        g_part_msum[blk]  = sm;
        g_part_mcnt[blk]  = cn;
    }
}

// ============================================================
// Kernel 2: CRF forward recurrence (linear domain, lazy renorm)
//   branchless steps; 128 blocks x 64 threads, 1 warp per batch
// ============================================================
__global__ void __launch_bounds__(64)
crf_kernel(const float* __restrict__ trans, const float* __restrict__ start,
           const float* __restrict__ endt, const int* __restrict__ mask)
{
    const unsigned FULL = 0xffffffffu;
    int b = blockIdx.x * 2 + (threadIdx.x >> 5);
    int j = threadIdx.x & 31;
    bool act = (j < TT);

    // E[i] = exp(transitions[i][j]) held in registers (column j)
    float Ecol[TT];
    #pragma unroll
    for (int i = 0; i < TT; i++)
        Ecol[i] = act ? __expf(__ldg(trans + i * TT + j)) : 0.0f;
    float eend = act ? __expf(__ldg(endt + j)) : 0.0f;

    const float* eb = g_eem + (size_t)b * (SS * EST);
    const int4* mb = reinterpret_cast<const int4*>(mask + b * SS);

    float bufA[8], bufB[8];
    int   mA[8],  mB[8];

    #pragma unroll
    for (int d = 0; d < 8; d++)
        bufA[d] = act ? __ldg(eb + d * EST + j) : 0.0f;
    {
        int4 a = __ldg(mb + 0), c = __ldg(mb + 1);
        mA[0]=a.x; mA[1]=a.y; mA[2]=a.z; mA[3]=a.w;
        mA[4]=c.x; mA[5]=c.y; mA[6]=c.z; mA[7]=c.w;
    }

    // step 0 init: p = eem0 * exp(start); row-max offsets live in msum
    float p = act ? bufA[0] * __expf(__ldg(start + j)) : 0.0f;
    float C = 0.0f;
    float r  = __shfl_sync(FULL, p, 0);
    float sc = __fdividef(1.0f, r);
    float lr = __logf(r);

    // branchless step: when masked, p unchanged -> recomputed sc/lr identical
    auto step = [&](float eemv, int mkv) {
        float mkf = (mkv != 0) ? 1.0f : 0.0f;
        float a[4] = {0.f, 0.f, 0.f, 0.f};
        #pragma unroll
        for (int i = 0; i < TT; i++)
            a[i & 3] = fmaf(__shfl_sync(FULL, p, i), Ecol[i], a[i & 3]);
        float q = (a[0] + a[1]) + (a[2] + a[3]);
        float pn = q * (eemv * sc);
        p = (mkv != 0) ? pn : p;       // FSEL, no branch
        C = fmaf(mkf, lr, C);
        r  = __shfl_sync(FULL, p, 0);
        sc = __fdividef(1.0f, r);
        lr = __logf(r);
    };

    #define PREFETCH(cidx, BUF, MARR)                                          \
        do {                                                                    \
            _Pragma("unroll")                                                   \
            for (int d = 0; d < 8; d++)                                         \
                BUF[d] = act ? __ldg(eb + ((cidx) * 8 + d) * EST + j) : 0.0f;   \
            int4 _a = __ldg(mb + 2 * (cidx)), _c = __ldg(mb + 2 * (cidx) + 1);  \
            MARR[0]=_a.x; MARR[1]=_a.y; MARR[2]=_a.z; MARR[3]=_a.w;             \
            MARR[4]=_c.x; MARR[5]=_c.y; MARR[6]=_c.z; MARR[7]=_c.w;             \
        } while (0)

    #define PROCESS(BUF, MARR)                                                  \
        do {                                                                    \
            _Pragma("unroll")                                                   \
            for (int d = 0; d < 8; d++) step(BUF[d], MARR[d]);                  \
        } while (0)

    // prefetch chunk 1, process chunk 0 steps 1..7
    PREFETCH(1, bufB, mB);
    #pragma unroll
    for (int d = 1; d < 8; d++) step(bufA[d], mA[d]);

    // main: chunks 1..62 double-buffered, chunk 63 tail
    for (int cc = 1; cc < 63; cc += 2) {
        PREFETCH(cc + 1, bufA, mA);
        PROCESS(bufB, mB);
        PREFETCH(cc + 2, bufB, mB);
        PROCESS(bufA, mA);
    }
    PROCESS(bufB, mB);

    // denom (minus msum offset) = C + log(sum_j p_j * exp(end_j))
    float term = p * eend;   // lanes >= 17 contribute 0
    #pragma unroll
    for (int off = 16; off; off >>= 1)
        term += __shfl_xor_sync(FULL, term, off);
    if (j == 0) g_denom[b] = C + __logf(term);

    #undef PREFETCH
    #undef PROCESS
}

// ============================================================
// Kernel 3: finalize  out = -mean(score - denom)
// ============================================================
__global__ void __launch_bounds__(256)
fin_kernel(const int* __restrict__ labels, const float* __restrict__ endt,
           float* __restrict__ out)
{
    __shared__ float sred[256];
    int b = threadIdx.x;
    int cnt  = g_part_mcnt[2 * b] + g_part_mcnt[2 * b + 1];
    int lt   = __ldg(labels + b * SS + (cnt - 1));
    float score = g_part_score[2 * b] + g_part_score[2 * b + 1] + __ldg(endt + lt);
    float denom = g_denom[b] + g_part_msum[2 * b] + g_part_msum[2 * b + 1];
    sred[b] = score - denom;
    __syncthreads();
    #pragma unroll
    for (int off = 128; off; off >>= 1) {
        if (b < off) sred[b] += sred[b + off];
        __syncthreads();
    }
    if (b == 0) out[0] = -sred[0] * (1.0f / BB);
}

// ============================================================
extern "C" void kernel_launch(void* const* d_in, const int* in_sizes, int n_in,
                              void* d_out, int out_size)
{
    const float* data   = (const float*)d_in[0];
    const int*   labels = (const int*)d_in[1];
    const int*   mask   = (const int*)d_in[2];
    const float* W      = (const float*)d_in[3];
    const float* bias   = (const float*)d_in[4];
    const float* start  = (const float*)d_in[5];
    const float* endt   = (const float*)d_in[6];
    const float* trans  = (const float*)d_in[7];

    // smem: W (68KB) + data tile (32KB) + reduction tail
    const int smem = (TT * DD + 256 * 32) * 4 + 128;   // 102528 bytes
    cudaFuncSetAttribute(emis_kernel,
                         cudaFuncAttributeMaxDynamicSharedMemorySize, smem);

    emis_kernel<<<512, 128, smem>>>(data, labels, mask, W, bias, start, trans);
    crf_kernel<<<BB / 2, 64>>>(trans, start, endt, mask);
    fin_kernel<<<1, 256>>>(labels, endt, (float*)d_out);
}

// round 6
// speedup vs baseline: 1.2357x; 1.2357x over previous
#include <cuda_runtime.h>
#include <cuda_bf16.h>
#include <cstdint>

#define BB 256
#define SS 512
#define DD 1024
#define TT 17
#define EST 20   // padded eem row stride (16B-aligned rows)

// ---------------- device scratch (no allocations allowed) ----------------
__device__ float g_eem[(size_t)BB * SS * EST];  // exp(em - rowmax), 10.5 MB
__device__ float g_part_score[512];             // per-block numerator partials
__device__ float g_part_msum[512];              // per-block sum of masked row-maxes
__device__ int   g_part_mcnt[512];              // per-block mask counts
__device__ float g_denom[BB];                   // log partition minus msum offset

__device__ __forceinline__ void fma2(unsigned long long &acc,
                                     unsigned long long a,
                                     unsigned long long b) {
    asm("fma.rn.f32x2 %0, %1, %2, %0;" : "+l"(acc) : "l"(a), "l"(b));
}

// ============================================================
// Kernel 1: emissions GEMM + eem/rowmax + numerator partials
//   512 blocks x 128 threads; warp owns 64 rows (2 rows/lane) and a
//   PRIVATE smem staging buffer -> no block barriers in the hot loop.
// ============================================================
__global__ void __launch_bounds__(128, 2)
emis_kernel(const float* __restrict__ data, const int* __restrict__ labels,
            const int* __restrict__ mask, const float* __restrict__ W,
            const float* __restrict__ bias, const float* __restrict__ start,
            const float* __restrict__ trans)
{
    extern __shared__ float smem[];
    float* sW  = smem;                       // 17*1024 floats (68 KB)
    const int tid = threadIdx.x;
    const int blk = blockIdx.x;              // half-batch index
    const int w   = tid >> 5;
    const int l   = tid & 31;
    float* sDw = smem + TT * DD + w * 2048;  // 8 KB per warp
    float* red = smem + TT * DD + 8192;      // reduction tail

    // cooperative load of W [T, D] into shared (float4)
    const float4* W4 = reinterpret_cast<const float4*>(W);
    float4* sW4 = reinterpret_cast<float4*>(sW);
    #pragma unroll 4
    for (int i = tid; i < TT * DD / 4; i += 128) sW4[i] = __ldg(W4 + i);

    // staging geometry: warp covers rows [blk*256 + w*64, +64)
    // LDG i (i=0..15): lane l -> row 4i + (l>>3), quad (l&7)
    const int rq = l >> 3;                    // 0..3
    const int q  = l & 7;                     // 0..7
    const float4* dq = reinterpret_cast<const float4*>(data);
    const long g0 = (long)(blk * 256 + w * 64 + rq) * 256 + q;  // float4 units
    const int base_e = 32 * rq + ((q ^ rq) << 2);        // even i (row&4==0)
    const int base_o = 32 * rq + ((q ^ (rq + 4)) << 2);  // odd  i (row&4==4)

    // prefetch tile 0 (16 LDG.128, coalesced: 4 lines each)
    float4 buf[16];
    #pragma unroll
    for (int i = 0; i < 16; i++) buf[i] = __ldg(dq + g0 + (long)i * 1024);

    __syncthreads();   // W ready

    unsigned long long acc[2][TT];
    #pragma unroll
    for (int r = 0; r < 2; r++)
        #pragma unroll
        for (int t = 0; t < TT; t++) acc[r][t] = 0ull;

    const int sw = l & 7;                         // compute-side swizzle key
    float* d0p = sDw + l * 32;                    // row l
    float* d1p = sDw + (l + 32) * 32;             // row l+32 (same swizzle key)
    const ulonglong2* sWv = reinterpret_cast<const ulonglong2*>(sW);

    for (int t = 0; t < 32; t++) {
        // store staged regs into warp-private smem (swizzled)
        #pragma unroll
        for (int i = 0; i < 16; i++)
            *reinterpret_cast<float4*>(sDw + 128 * i + ((i & 1) ? base_o : base_e)) = buf[i];
        __syncwarp();

        // prefetch next tile
        if (t < 31) {
            #pragma unroll
            for (int i = 0; i < 16; i++)
                buf[i] = __ldg(dq + g0 + (t + 1) * 8 + (long)i * 1024);
        }

        // compute 8 k-quads of this tile
        #pragma unroll
        for (int kk = 0; kk < 8; kk++) {
            float4 d0 = *reinterpret_cast<const float4*>(d0p + ((kk ^ sw) << 2));
            float4 d1 = *reinterpret_cast<const float4*>(d1p + ((kk ^ sw) << 2));
            unsigned long long d0x = *reinterpret_cast<unsigned long long*>(&d0.x);
            unsigned long long d0y = *reinterpret_cast<unsigned long long*>(&d0.z);
            unsigned long long d1x = *reinterpret_cast<unsigned long long*>(&d1.x);
            unsigned long long d1y = *reinterpret_cast<unsigned long long*>(&d1.z);
            #pragma unroll
            for (int tg = 0; tg < TT; tg++) {
                ulonglong2 wv = sWv[tg * 256 + t * 8 + kk];
                fma2(acc[0][tg], d0x, wv.x);
                fma2(acc[0][tg], d0y, wv.y);
                fma2(acc[1][tg], d1x, wv.x);
                fma2(acc[1][tg], d1y, wv.y);
            }
        }
        __syncwarp();   // reads done before next STS overwrites
    }

    // ---- epilogue: per-row max/exp/store + numerator accumulation ----
    float contrib = 0.0f, msum_t = 0.0f;
    int mcnt_t = 0;

    #pragma unroll
    for (int r = 0; r < 2; r++) {
        int row = blk * 256 + w * 64 + l + r * 32;   // global row
        int s   = row & (SS - 1);

        float emv[TT];
        float m = -1e30f;
        #pragma unroll
        for (int tg = 0; tg < TT; tg++) {
            float lo = __uint_as_float((unsigned)(acc[r][tg] & 0xffffffffull));
            float hi = __uint_as_float((unsigned)(acc[r][tg] >> 32));
            emv[tg] = lo + hi + __ldg(bias + tg);
            m = fmaxf(m, emv[tg]);
        }

        float e[TT];
        #pragma unroll
        for (int tg = 0; tg < TT; tg++) e[tg] = __expf(emv[tg] - m);

        float4* o4 = reinterpret_cast<float4*>(g_eem + (size_t)row * EST);
        o4[0] = make_float4(e[0],  e[1],  e[2],  e[3]);
        o4[1] = make_float4(e[4],  e[5],  e[6],  e[7]);
        o4[2] = make_float4(e[8],  e[9],  e[10], e[11]);
        o4[3] = make_float4(e[12], e[13], e[14], e[15]);
        o4[4] = make_float4(e[16], 0.0f,  0.0f,  0.0f);

        int lab = __ldg(labels + row);
        float em_lab = 0.0f;
        #pragma unroll
        for (int tg = 0; tg < TT; tg++) em_lab = (lab == tg) ? emv[tg] : em_lab;

        float mk = (__ldg(mask + row) != 0) ? 1.0f : 0.0f;
        if (s == 0) {
            contrib += __ldg(start + lab) + em_lab;   // always included
        } else {
            int prev = __ldg(labels + row - 1);
            contrib += mk * (__ldg(trans + prev * TT + lab) + em_lab);
        }
        msum_t += mk * m;
        mcnt_t += (mk > 0.0f) ? 1 : 0;
    }

    // ---- block reduction (deterministic, no atomics); 4 warps ----
    const unsigned FULL = 0xffffffffu;
    #pragma unroll
    for (int off = 16; off; off >>= 1) {
        contrib += __shfl_xor_sync(FULL, contrib, off);
        msum_t  += __shfl_xor_sync(FULL, msum_t, off);
        mcnt_t  += __shfl_xor_sync(FULL, mcnt_t, off);
    }
    if (l == 0) {
        red[w]     = contrib;
        red[4 + w] = msum_t;
        reinterpret_cast<int*>(red)[8 + w] = mcnt_t;
    }
    __syncthreads();
    if (tid == 0) {
        float sc = 0.0f, sm = 0.0f; int cn = 0;
        #pragma unroll
        for (int ww = 0; ww < 4; ww++) {
            sc += red[ww];
            sm += red[4 + ww];
            cn += reinterpret_cast<int*>(red)[8 + ww];
        }
        g_part_score[blk] = sc;
        g_part_msum[blk]  = sm;
        g_part_mcnt[blk]  = cn;
    }
}

// ============================================================
// Kernel 2: CRF forward recurrence (linear domain, lazy renorm)
//   REVERTED to R4 (measured-best): branchy steps, 128 blocks x 64
// ============================================================
__global__ void __launch_bounds__(64)
crf_kernel(const float* __restrict__ trans, const float* __restrict__ start,
           const float* __restrict__ endt, const int* __restrict__ mask)
{
    const unsigned FULL = 0xffffffffu;
    int b = blockIdx.x * 2 + (threadIdx.x >> 5);
    int j = threadIdx.x & 31;
    bool act = (j < TT);

    // E[i] = exp(transitions[i][j]) held in registers (column j)
    float Ecol[TT];
    #pragma unroll
    for (int i = 0; i < TT; i++)
        Ecol[i] = act ? __expf(__ldg(trans + i * TT + j)) : 0.0f;
    float eend = act ? __expf(__ldg(endt + j)) : 0.0f;

    const float* eb = g_eem + (size_t)b * (SS * EST);
    const int4* mb = reinterpret_cast<const int4*>(mask + b * SS);

    float bufA[8], bufB[8];
    int   mA[8],  mB[8];

    #pragma unroll
    for (int d = 0; d < 8; d++)
        bufA[d] = act ? __ldg(eb + d * EST + j) : 0.0f;
    {
        int4 a = __ldg(mb + 0), c = __ldg(mb + 1);
        mA[0]=a.x; mA[1]=a.y; mA[2]=a.z; mA[3]=a.w;
        mA[4]=c.x; mA[5]=c.y; mA[6]=c.z; mA[7]=c.w;
    }

    // step 0 init: p = eem0 * exp(start); row-max offsets live in msum
    float p = act ? bufA[0] * __expf(__ldg(start + j)) : 0.0f;
    float C = 0.0f;
    float r  = __shfl_sync(FULL, p, 0);
    float sc = __fdividef(1.0f, r);
    float lr = __logf(r);

    auto step = [&](float eemv, int mkv) {
        if (mkv != 0) {  // warp-uniform
            float a[4] = {0.f, 0.f, 0.f, 0.f};
            #pragma unroll
            for (int i = 0; i < TT; i++)
                a[i & 3] = fmaf(__shfl_sync(FULL, p, i), Ecol[i], a[i & 3]);
            float q = (a[0] + a[1]) + (a[2] + a[3]);
            p = q * (eemv * sc);   // apply previous step's scale lazily
            C += lr;
            r  = __shfl_sync(FULL, p, 0);
            sc = __fdividef(1.0f, r);
            lr = __logf(r);
        }
    };

    #define PREFETCH(cidx, BUF, MARR)                                          \
        do {                                                                    \
            _Pragma("unroll")                                                   \
            for (int d = 0; d < 8; d++)                                         \
                BUF[d] = act ? __ldg(eb + ((cidx) * 8 + d) * EST + j) : 0.0f;   \
            int4 _a = __ldg(mb + 2 * (cidx)), _c = __ldg(mb + 2 * (cidx) + 1);  \
            MARR[0]=_a.x; MARR[1]=_a.y; MARR[2]=_a.z; MARR[3]=_a.w;             \
            MARR[4]=_c.x; MARR[5]=_c.y; MARR[6]=_c.z; MARR[7]=_c.w;             \
        } while (0)

    #define PROCESS(BUF, MARR)                                                  \
        do {                                                                    \
            _Pragma("unroll")                                                   \
            for (int d = 0; d < 8; d++) step(BUF[d], MARR[d]);                  \
        } while (0)

    // prefetch chunk 1, process chunk 0 steps 1..7
    PREFETCH(1, bufB, mB);
    #pragma unroll
    for (int d = 1; d < 8; d++) step(bufA[d], mA[d]);

    // main: chunks 1..62 double-buffered, chunk 63 tail
    for (int cc = 1; cc < 63; cc += 2) {
        PREFETCH(cc + 1, bufA, mA);
        PROCESS(bufB, mB);
        PREFETCH(cc + 2, bufB, mB);
        PROCESS(bufA, mA);
    }
    PROCESS(bufB, mB);

    // denom (minus msum offset) = C + log(sum_j p_j * exp(end_j))
    float term = p * eend;   // lanes >= 17 contribute 0
    #pragma unroll
    for (int off = 16; off; off >>= 1)
        term += __shfl_xor_sync(FULL, term, off);
    if (j == 0) g_denom[b] = C + __logf(term);

    #undef PREFETCH
    #undef PROCESS
}

// ============================================================
// Kernel 3: finalize  out = -mean(score - denom)
// ============================================================
__global__ void __launch_bounds__(256)
fin_kernel(const int* __restrict__ labels, const float* __restrict__ endt,
           float* __restrict__ out)
{
    __shared__ float sred[256];
    int b = threadIdx.x;
    int cnt  = g_part_mcnt[2 * b] + g_part_mcnt[2 * b + 1];
    int lt   = __ldg(labels + b * SS + (cnt - 1));
    float score = g_part_score[2 * b] + g_part_score[2 * b + 1] + __ldg(endt + lt);
    float denom = g_denom[b] + g_part_msum[2 * b] + g_part_msum[2 * b + 1];
    sred[b] = score - denom;
    __syncthreads();
    #pragma unroll
    for (int off = 128; off; off >>= 1) {
        if (b < off) sred[b] += sred[b + off];
        __syncthreads();
    }
    if (b == 0) out[0] = -sred[0] * (1.0f / BB);
}

// ============================================================
extern "C" void kernel_launch(void* const* d_in, const int* in_sizes, int n_in,
                              void* d_out, int out_size)
{
    const float* data   = (const float*)d_in[0];
    const int*   labels = (const int*)d_in[1];
    const int*   mask   = (const int*)d_in[2];
    const float* W      = (const float*)d_in[3];
    const float* bias   = (const float*)d_in[4];
    const float* start  = (const float*)d_in[5];
    const float* endt   = (const float*)d_in[6];
    const float* trans  = (const float*)d_in[7];

    // smem: W (68KB) + 4 warp-private tiles (32KB) + reduction tail
    const int smem = (TT * DD + 4 * 2048) * 4 + 64;   // 102464 bytes
    cudaFuncSetAttribute(emis_kernel,
                         cudaFuncAttributeMaxDynamicSharedMemorySize, smem);

    emis_kernel<<<512, 128, smem>>>(data, labels, mask, W, bias, start, trans);
    crf_kernel<<<BB / 2, 64>>>(trans, start, endt, mask);
    fin_kernel<<<1, 256>>>(labels, endt, (float*)d_out);
}

// round 8
// speedup vs baseline: 1.3311x; 1.0772x over previous
#include <cuda_runtime.h>
#include <cuda_bf16.h>
#include <cstdint>

#define BB 256
#define SS 512
#define DD 1024
#define TT 17
#define EST 20   // padded eem row stride (16B-aligned rows)

// ---------------- device scratch (no allocations allowed) ----------------
__device__ float g_eem[(size_t)BB * SS * EST];  // exp(em - rowmax), 10.5 MB
__device__ float g_part_score[1024];            // per-CTA numerator partials
__device__ float g_part_msum[1024];             // per-CTA sum of masked row-maxes
__device__ int   g_part_mcnt[1024];             // per-CTA mask counts
__device__ float g_denom[BB];                   // log partition minus msum offset

// ---------------- smem layout (bytes) ----------------
#define SM_B    0                       // W bf16: 24 n-rows x 1024 k = 48 KB
#define SM_A    49152                   // 4 warps x 2 bufs x 4 KB = 32 KB
#define SM_D    SM_A                    // D reuse: 128 x 26 fp32 = 13312 B
#define SM_RED  (SM_A + 32768)          // 81920
#define SM_TOT  (SM_RED + 64)           // 81984

__device__ __forceinline__ uint2 cvt_f4_bf16x4(float4 f) {
    uint2 r;
    // low 16 bits = earlier k element
    asm("cvt.rn.bf16x2.f32 %0, %1, %2;" : "=r"(r.x) : "f"(f.y), "f"(f.x));
    asm("cvt.rn.bf16x2.f32 %0, %1, %2;" : "=r"(r.y) : "f"(f.w), "f"(f.z));
    return r;
}

__device__ __forceinline__ void mma16816(float* d, const uint32_t* a,
                                         const uint32_t* b) {
    asm volatile(
        "mma.sync.aligned.m16n8k16.row.col.f32.bf16.bf16.f32 "
        "{%0,%1,%2,%3}, {%4,%5,%6,%7}, {%8,%9}, {%0,%1,%2,%3};"
        : "+f"(d[0]), "+f"(d[1]), "+f"(d[2]), "+f"(d[3])
        : "r"(a[0]), "r"(a[1]), "r"(a[2]), "r"(a[3]), "r"(b[0]), "r"(b[1]));
}

// ============================================================
// Kernel 1: HMMA emissions GEMM + eem/rowmax + numerator partials
//   1024 CTAs x 128 threads; warp owns 32 rows, private staging bufs.
// ============================================================
__global__ void __launch_bounds__(128, 2)
emis_kernel(const float* __restrict__ data, const int* __restrict__ labels,
            const int* __restrict__ mask, const float* __restrict__ W,
            const float* __restrict__ bias, const float* __restrict__ start,
            const float* __restrict__ trans)
{
    extern __shared__ char smem[];
    const int tid = threadIdx.x;
    const int blk = blockIdx.x;
    const int w   = tid >> 5;
    const int l   = tid & 31;

    // ---- stage B = W as bf16 [24 n x 1024 k], swizzled; rows 17..23 zero ----
    for (int i = tid; i < 24 * 2048 / 4; i += 128)
        reinterpret_cast<uint32_t*>(smem + SM_B)[i] = 0u;
    __syncthreads();
    for (int i = tid; i < TT * DD; i += 128) {
        int n = i >> 10, k = i & 1023;
        uint32_t off = (uint32_t)(n * 2048 + ((2 * k) ^ ((n & 7) << 4)));
        *reinterpret_cast<__nv_bfloat16*>(smem + SM_B + off) =
            __float2bfloat16(__ldg(W + i));
    }

    // ---- A staging geometry (warp-private) ----
    const int lr8 = l >> 4;                 // 0..1
    const int q   = l & 15;                 // float4 col within 64-float chunk
    const float4* dq = reinterpret_cast<const float4*>(data);
    const long g0 = (long)(blk * 128 + w * 32 + lr8) * 256 + q;  // float4 units
    char* sAw = smem + SM_A + w * 8192;

    // prefetch chunk 0
    uint2 pk[16];
    #pragma unroll
    for (int i = 0; i < 16; i++)
        pk[i] = cvt_f4_bf16x4(__ldg(dq + g0 + (long)i * 512));

    __syncthreads();   // B ready

    float acc[2][3][4];
    #pragma unroll
    for (int mt = 0; mt < 2; mt++)
        #pragma unroll
        for (int nt = 0; nt < 3; nt++)
            #pragma unroll
            for (int x = 0; x < 4; x++) acc[mt][nt][x] = 0.0f;

    const int rk = l >> 2;                   // fragment row & swizzle key
    const int cx = (l & 3) * 4;
    const uint32_t keysh = (uint32_t)rk << 4;
    char* sB = smem + SM_B;

    #pragma unroll 1
    for (int c = 0; c < 16; c++) {
        char* buf = sAw + (c & 1) * 4096;
        // STS staged regs (swizzled): row i*2+lr8, key = ((i&3)*2+lr8)
        #pragma unroll
        for (int i = 0; i < 16; i++)
            *reinterpret_cast<uint2*>(
                buf + (i * 2 + lr8) * 128 +
                ((q * 8) ^ (((i & 3) * 2 + lr8) << 4))) = pk[i];
        __syncwarp();

        // prefetch next chunk
        if (c < 15) {
            #pragma unroll
            for (int i = 0; i < 16; i++)
                pk[i] = cvt_f4_bf16x4(__ldg(dq + g0 + (long)i * 512 + (c + 1) * 16));
        }

        // 4 ksteps of k=16
        #pragma unroll
        for (int ks = 0; ks < 4; ks++) {
            const uint32_t a0o = (uint32_t)(rk * 128) + (((uint32_t)(ks * 32 + cx)) ^ keysh);
            uint32_t aA[2][4];
            #pragma unroll
            for (int mt = 0; mt < 2; mt++) {
                char* bm = buf + mt * 2048;
                aA[mt][0] = *reinterpret_cast<uint32_t*>(bm + a0o);
                aA[mt][1] = *reinterpret_cast<uint32_t*>(bm + a0o + 1024);
                aA[mt][2] = *reinterpret_cast<uint32_t*>(bm + (a0o ^ 16));
                aA[mt][3] = *reinterpret_cast<uint32_t*>(bm + (a0o ^ 16) + 1024);
            }
            #pragma unroll
            for (int nt = 0; nt < 3; nt++) {
                const uint32_t b0o = (uint32_t)((nt * 8 + rk) * 2048) +
                    (((uint32_t)(c * 128 + ks * 32 + cx)) ^ keysh);
                uint32_t bb[2];
                bb[0] = *reinterpret_cast<uint32_t*>(sB + b0o);
                bb[1] = *reinterpret_cast<uint32_t*>(sB + (b0o ^ 16));
                mma16816(acc[0][nt], aA[0], bb);
                mma16816(acc[1][nt], aA[1], bb);
            }
        }
        __syncwarp();
    }

    // ---- D -> smem (stride 26 floats), then per-thread row epilogue ----
    __syncthreads();   // all warps done with A region
    float* sD = reinterpret_cast<float*>(smem + SM_D);
    #pragma unroll
    for (int mt = 0; mt < 2; mt++)
        #pragma unroll
        for (int nt = 0; nt < 3; nt++) {
            int r  = w * 32 + mt * 16 + rk;
            int cb = nt * 8 + (l & 3) * 2;
            *reinterpret_cast<float2*>(sD + r * 26 + cb) =
                make_float2(acc[mt][nt][0], acc[mt][nt][1]);
            *reinterpret_cast<float2*>(sD + (r + 8) * 26 + cb) =
                make_float2(acc[mt][nt][2], acc[mt][nt][3]);
        }
    __syncthreads();

    const int row = blk * 128 + tid;     // global row
    const int s   = row & (SS - 1);

    float emv[TT];
    float m = -1e30f;
    #pragma unroll
    for (int t = 0; t < TT; t++) {
        emv[t] = sD[tid * 26 + t] + __ldg(bias + t);
        m = fmaxf(m, emv[t]);
    }
    float e[TT];
    #pragma unroll
    for (int t = 0; t < TT; t++) e[t] = __expf(emv[t] - m);

    float4* o4 = reinterpret_cast<float4*>(g_eem + (size_t)row * EST);
    o4[0] = make_float4(e[0],  e[1],  e[2],  e[3]);
    o4[1] = make_float4(e[4],  e[5],  e[6],  e[7]);
    o4[2] = make_float4(e[8],  e[9],  e[10], e[11]);
    o4[3] = make_float4(e[12], e[13], e[14], e[15]);
    o4[4] = make_float4(e[16], 0.0f,  0.0f,  0.0f);

    int lab = __ldg(labels + row);
    float em_lab = 0.0f;
    #pragma unroll
    for (int t = 0; t < TT; t++) em_lab = (lab == t) ? emv[t] : em_lab;

    float mk = (__ldg(mask + row) != 0) ? 1.0f : 0.0f;
    float contrib;
    if (s == 0) {
        contrib = __ldg(start + lab) + em_lab;       // always included
    } else {
        int prev = __ldg(labels + row - 1);
        contrib = mk * (__ldg(trans + prev * TT + lab) + em_lab);
    }
    float msum_t = mk * m;
    int   mcnt_t = (mk > 0.0f) ? 1 : 0;

    // block reduction (deterministic)
    const unsigned FULL = 0xffffffffu;
    #pragma unroll
    for (int off = 16; off; off >>= 1) {
        contrib += __shfl_xor_sync(FULL, contrib, off);
        msum_t  += __shfl_xor_sync(FULL, msum_t, off);
        mcnt_t  += __shfl_xor_sync(FULL, mcnt_t, off);
    }
    float* red = reinterpret_cast<float*>(smem + SM_RED);
    if (l == 0) {
        red[w]     = contrib;
        red[4 + w] = msum_t;
        reinterpret_cast<int*>(red)[8 + w] = mcnt_t;
    }
    __syncthreads();
    if (tid == 0) {
        float sc = 0.0f, sm = 0.0f; int cn = 0;
        #pragma unroll
        for (int ww = 0; ww < 4; ww++) {
            sc += red[ww];
            sm += red[4 + ww];
            cn += reinterpret_cast<int*>(red)[8 + ww];
        }
        g_part_score[blk] = sc;
        g_part_msum[blk]  = sm;
        g_part_mcnt[blk]  = cn;
    }
}

// ============================================================
// Kernel 2: CRF forward recurrence (linear domain, lazy renorm)
//   measured-best R4 form: branchy steps, 128 blocks x 64 threads
// ============================================================
__global__ void __launch_bounds__(64)
crf_kernel(const float* __restrict__ trans, const float* __restrict__ start,
           const float* __restrict__ endt, const int* __restrict__ mask)
{
    const unsigned FULL = 0xffffffffu;
    int b = blockIdx.x * 2 + (threadIdx.x >> 5);
    int j = threadIdx.x & 31;
    bool act = (j < TT);

    float Ecol[TT];
    #pragma unroll
    for (int i = 0; i < TT; i++)
        Ecol[i] = act ? __expf(__ldg(trans + i * TT + j)) : 0.0f;
    float eend = act ? __expf(__ldg(endt + j)) : 0.0f;

    const float* eb = g_eem + (size_t)b * (SS * EST);
    const int4* mb = reinterpret_cast<const int4*>(mask + b * SS);

    float bufA[8], bufB[8];
    int   mA[8],  mB[8];

    #pragma unroll
    for (int d = 0; d < 8; d++)
        bufA[d] = act ? __ldg(eb + d * EST + j) : 0.0f;
    {
        int4 a = __ldg(mb + 0), c = __ldg(mb + 1);
        mA[0]=a.x; mA[1]=a.y; mA[2]=a.z; mA[3]=a.w;
        mA[4]=c.x; mA[5]=c.y; mA[6]=c.z; mA[7]=c.w;
    }

    float p = act ? bufA[0] * __expf(__ldg(start + j)) : 0.0f;
    float C = 0.0f;
    float r  = __shfl_sync(FULL, p, 0);
    float sc = __fdividef(1.0f, r);
    float lr = __logf(r);

    auto step = [&](float eemv, int mkv) {
        if (mkv != 0) {  // warp-uniform
            float a[4] = {0.f, 0.f, 0.f, 0.f};
            #pragma unroll
            for (int i = 0; i < TT; i++)
                a[i & 3] = fmaf(__shfl_sync(FULL, p, i), Ecol[i], a[i & 3]);
            float q = (a[0] + a[1]) + (a[2] + a[3]);
            p = q * (eemv * sc);
            C += lr;
            r  = __shfl_sync(FULL, p, 0);
            sc = __fdividef(1.0f, r);
            lr = __logf(r);
        }
    };

    #define PREFETCH(cidx, BUF, MARR)                                          \
        do {                                                                    \
            _Pragma("unroll")                                                   \
            for (int d = 0; d < 8; d++)                                         \
                BUF[d] = act ? __ldg(eb + ((cidx) * 8 + d) * EST + j) : 0.0f;   \
            int4 _a = __ldg(mb + 2 * (cidx)), _c = __ldg(mb + 2 * (cidx) + 1);  \
            MARR[0]=_a.x; MARR[1]=_a.y; MARR[2]=_a.z; MARR[3]=_a.w;             \
            MARR[4]=_c.x; MARR[5]=_c.y; MARR[6]=_c.z; MARR[7]=_c.w;             \
        } while (0)

    #define PROCESS(BUF, MARR)                                                  \
        do {                                                                    \
            _Pragma("unroll")                                                   \
            for (int d = 0; d < 8; d++) step(BUF[d], MARR[d]);                  \
        } while (0)

    PREFETCH(1, bufB, mB);
    #pragma unroll
    for (int d = 1; d < 8; d++) step(bufA[d], mA[d]);

    for (int cc = 1; cc < 63; cc += 2) {
        PREFETCH(cc + 1, bufA, mA);
        PROCESS(bufB, mB);
        PREFETCH(cc + 2, bufB, mB);
        PROCESS(bufA, mA);
    }
    PROCESS(bufB, mB);

    float term = p * eend;
    #pragma unroll
    for (int off = 16; off; off >>= 1)
        term += __shfl_xor_sync(FULL, term, off);
    if (j == 0) g_denom[b] = C + __logf(term);

    #undef PREFETCH
    #undef PROCESS
}

// ============================================================
// Kernel 3: finalize  out = -mean(score - denom)
// ============================================================
__global__ void __launch_bounds__(256)
fin_kernel(const int* __restrict__ labels, const float* __restrict__ endt,
           float* __restrict__ out)
{
    __shared__ float sred[256];
    int b = threadIdx.x;
    int cnt = 0;
    float psc = 0.0f, pms = 0.0f;
    #pragma unroll
    for (int k = 0; k < 4; k++) {
        cnt += g_part_mcnt[4 * b + k];
        psc += g_part_score[4 * b + k];
        pms += g_part_msum[4 * b + k];
    }
    int lt = __ldg(labels + b * SS + (cnt - 1));
    float score = psc + __ldg(endt + lt);
    float denom = g_denom[b] + pms;
    sred[b] = score - denom;
    __syncthreads();
    #pragma unroll
    for (int off = 128; off; off >>= 1) {
        if (b < off) sred[b] += sred[b + off];
        __syncthreads();
    }
    if (b == 0) out[0] = -sred[0] * (1.0f / BB);
}

// ============================================================
extern "C" void kernel_launch(void* const* d_in, const int* in_sizes, int n_in,
                              void* d_out, int out_size)
{
    const float* data   = (const float*)d_in[0];
    const int*   labels = (const int*)d_in[1];
    const int*   mask   = (const int*)d_in[2];
    const float* W      = (const float*)d_in[3];
    const float* bias   = (const float*)d_in[4];
    const float* start  = (const float*)d_in[5];
    const float* endt   = (const float*)d_in[6];
    const float* trans  = (const float*)d_in[7];

    cudaFuncSetAttribute(emis_kernel,
                         cudaFuncAttributeMaxDynamicSharedMemorySize, SM_TOT);

    emis_kernel<<<1024, 128, SM_TOT>>>(data, labels, mask, W, bias, start, trans);
    crf_kernel<<<BB / 2, 64>>>(trans, start, endt, mask);
    fin_kernel<<<1, 256>>>(labels, endt, (float*)d_out);
}

// round 9
// speedup vs baseline: 1.4734x; 1.1069x over previous
#include <cuda_runtime.h>
#include <cuda_bf16.h>
#include <cstdint>

#define BB 256
#define SS 512
#define DD 1024
#define TT 17
#define EST 20   // padded eem row stride (16B-aligned rows)

// ---------------- device scratch (no allocations allowed) ----------------
__device__ float g_eem[(size_t)BB * SS * EST];  // exp(em - rowmax), 10.5 MB
__device__ float g_part_score[1024];            // per-CTA numerator partials
__device__ float g_part_msum[1024];             // per-CTA sum of masked row-maxes
__device__ int   g_part_mcnt[1024];             // per-CTA mask counts
__device__ float g_denom[BB];                   // log partition minus msum offset

// ---------------- smem layout (bytes) ----------------
#define SM_B    0                       // W bf16: 24 n-rows x 1024 k = 48 KB
#define SM_A    49152                   // 4 warps x 1 buf x 4 KB = 16 KB
#define SM_D    SM_A                    // D reuse: 128 x 26 fp32 = 13312 B
#define SM_RED  (SM_A + 16384)          // 65536
#define SM_TOT  (SM_RED + 64)           // 65600

__device__ __forceinline__ uint2 cvt_f4_bf16x4(float4 f) {
    uint2 r;
    // low 16 bits = earlier k element
    asm("cvt.rn.bf16x2.f32 %0, %1, %2;" : "=r"(r.x) : "f"(f.y), "f"(f.x));
    asm("cvt.rn.bf16x2.f32 %0, %1, %2;" : "=r"(r.y) : "f"(f.w), "f"(f.z));
    return r;
}

__device__ __forceinline__ void mma16816(float* d, const uint32_t* a,
                                         const uint32_t* b) {
    asm volatile(
        "mma.sync.aligned.m16n8k16.row.col.f32.bf16.bf16.f32 "
        "{%0,%1,%2,%3}, {%4,%5,%6,%7}, {%8,%9}, {%0,%1,%2,%3};"
        : "+f"(d[0]), "+f"(d[1]), "+f"(d[2]), "+f"(d[3])
        : "r"(a[0]), "r"(a[1]), "r"(a[2]), "r"(a[3]), "r"(b[0]), "r"(b[1]));
}

// ============================================================
// Kernel 1: HMMA emissions GEMM + eem/rowmax + numerator partials
//   1024 CTAs x 128 threads; warp owns 32 rows, private staging buf.
//   Raw fp32 prefetch regs (no dependent CVT) keep 16 LDG.128 in flight.
// ============================================================
__global__ void __launch_bounds__(128, 2)
emis_kernel(const float* __restrict__ data, const int* __restrict__ labels,
            const int* __restrict__ mask, const float* __restrict__ W,
            const float* __restrict__ bias, const float* __restrict__ start,
            const float* __restrict__ trans)
{
    extern __shared__ char smem[];
    const int tid = threadIdx.x;
    const int blk = blockIdx.x;
    const int w   = tid >> 5;
    const int l   = tid & 31;

    // ---- stage B = W as bf16 [24 n x 1024 k], swizzled; rows 17..23 zero ----
    for (int i = tid; i < 24 * 2048 / 4; i += 128)
        reinterpret_cast<uint32_t*>(smem + SM_B)[i] = 0u;
    __syncthreads();
    for (int i = tid; i < TT * DD; i += 128) {
        int n = i >> 10, k = i & 1023;
        uint32_t off = (uint32_t)(n * 2048 + ((2 * k) ^ ((n & 7) << 4)));
        *reinterpret_cast<__nv_bfloat16*>(smem + SM_B + off) =
            __float2bfloat16(__ldg(W + i));
    }

    // ---- A staging geometry (warp-private, single 4 KB buffer) ----
    const int lr8 = l >> 4;                 // 0..1
    const int q   = l & 15;                 // float4 col within 64-float chunk
    const float4* dq = reinterpret_cast<const float4*>(data);
    const long g0 = (long)(blk * 128 + w * 32 + lr8) * 256 + q;  // float4 units
    char* buf = smem + SM_A + w * 4096;

    // prefetch chunk 0 RAW (no dependent ops -> all 16 LDGs in flight)
    float4 raw[16];
    #pragma unroll
    for (int i = 0; i < 16; i++)
        raw[i] = __ldg(dq + g0 + (long)i * 512);

    __syncthreads();   // B ready

    float acc[2][3][4];
    #pragma unroll
    for (int mt = 0; mt < 2; mt++)
        #pragma unroll
        for (int nt = 0; nt < 3; nt++)
            #pragma unroll
            for (int x = 0; x < 4; x++) acc[mt][nt][x] = 0.0f;

    const int rk = l >> 2;                   // fragment row & swizzle key
    const int cx = (l & 3) * 4;
    const uint32_t keysh = (uint32_t)rk << 4;
    char* sB = smem + SM_B;

    #pragma unroll 1
    for (int c = 0; c < 16; c++) {
        // CVT + STS of current chunk (consume raw regs)
        #pragma unroll
        for (int i = 0; i < 16; i++) {
            uint2 pk = cvt_f4_bf16x4(raw[i]);
            *reinterpret_cast<uint2*>(
                buf + (i * 2 + lr8) * 128 +
                ((q * 8) ^ (((i & 3) * 2 + lr8) << 4))) = pk;
        }
        __syncwarp();

        // prefetch next chunk RAW
        if (c < 15) {
            #pragma unroll
            for (int i = 0; i < 16; i++)
                raw[i] = __ldg(dq + g0 + (long)i * 512 + (c + 1) * 16);
        }

        // 4 ksteps of k=16
        #pragma unroll
        for (int ks = 0; ks < 4; ks++) {
            const uint32_t a0o = (uint32_t)(rk * 128) + (((uint32_t)(ks * 32 + cx)) ^ keysh);
            uint32_t aA[2][4];
            #pragma unroll
            for (int mt = 0; mt < 2; mt++) {
                char* bm = buf + mt * 2048;
                aA[mt][0] = *reinterpret_cast<uint32_t*>(bm + a0o);
                aA[mt][1] = *reinterpret_cast<uint32_t*>(bm + a0o + 1024);
                aA[mt][2] = *reinterpret_cast<uint32_t*>(bm + (a0o ^ 16));
                aA[mt][3] = *reinterpret_cast<uint32_t*>(bm + (a0o ^ 16) + 1024);
            }
            #pragma unroll
            for (int nt = 0; nt < 3; nt++) {
                const uint32_t b0o = (uint32_t)((nt * 8 + rk) * 2048) +
                    (((uint32_t)(c * 128 + ks * 32 + cx)) ^ keysh);
                uint32_t bb[2];
                bb[0] = *reinterpret_cast<uint32_t*>(sB + b0o);
                bb[1] = *reinterpret_cast<uint32_t*>(sB + (b0o ^ 16));
                mma16816(acc[0][nt], aA[0], bb);
                mma16816(acc[1][nt], aA[1], bb);
            }
        }
        __syncwarp();   // fragment reads done before next STS overwrites
    }

    // ---- D -> smem (stride 26 floats), then per-thread row epilogue ----
    __syncthreads();   // all warps done with A region
    float* sD = reinterpret_cast<float*>(smem + SM_D);
    #pragma unroll
    for (int mt = 0; mt < 2; mt++)
        #pragma unroll
        for (int nt = 0; nt < 3; nt++) {
            int r  = w * 32 + mt * 16 + rk;
            int cb = nt * 8 + (l & 3) * 2;
            *reinterpret_cast<float2*>(sD + r * 26 + cb) =
                make_float2(acc[mt][nt][0], acc[mt][nt][1]);
            *reinterpret_cast<float2*>(sD + (r + 8) * 26 + cb) =
                make_float2(acc[mt][nt][2], acc[mt][nt][3]);
        }
    __syncthreads();

    const int row = blk * 128 + tid;     // global row
    const int s   = row & (SS - 1);

    float emv[TT];
    float m = -1e30f;
    #pragma unroll
    for (int t = 0; t < TT; t++) {
        emv[t] = sD[tid * 26 + t] + __ldg(bias + t);
        m = fmaxf(m, emv[t]);
    }
    float e[TT];
    #pragma unroll
    for (int t = 0; t < TT; t++) e[t] = __expf(emv[t] - m);

    float4* o4 = reinterpret_cast<float4*>(g_eem + (size_t)row * EST);
    o4[0] = make_float4(e[0],  e[1],  e[2],  e[3]);
    o4[1] = make_float4(e[4],  e[5],  e[6],  e[7]);
    o4[2] = make_float4(e[8],  e[9],  e[10], e[11]);
    o4[3] = make_float4(e[12], e[13], e[14], e[15]);
    o4[4] = make_float4(e[16], 0.0f,  0.0f,  0.0f);

    int lab = __ldg(labels + row);
    float em_lab = 0.0f;
    #pragma unroll
    for (int t = 0; t < TT; t++) em_lab = (lab == t) ? emv[t] : em_lab;

    float mk = (__ldg(mask + row) != 0) ? 1.0f : 0.0f;
    float contrib;
    if (s == 0) {
        contrib = __ldg(start + lab) + em_lab;       // always included
    } else {
        int prev = __ldg(labels + row - 1);
        contrib = mk * (__ldg(trans + prev * TT + lab) + em_lab);
    }
    float msum_t = mk * m;
    int   mcnt_t = (mk > 0.0f) ? 1 : 0;

    // block reduction (deterministic)
    const unsigned FULL = 0xffffffffu;
    #pragma unroll
    for (int off = 16; off; off >>= 1) {
        contrib += __shfl_xor_sync(FULL, contrib, off);
        msum_t  += __shfl_xor_sync(FULL, msum_t, off);
        mcnt_t  += __shfl_xor_sync(FULL, mcnt_t, off);
    }
    float* red = reinterpret_cast<float*>(smem + SM_RED);
    if (l == 0) {
        red[w]     = contrib;
        red[4 + w] = msum_t;
        reinterpret_cast<int*>(red)[8 + w] = mcnt_t;
    }
    __syncthreads();
    if (tid == 0) {
        float sc = 0.0f, sm = 0.0f; int cn = 0;
        #pragma unroll
        for (int ww = 0; ww < 4; ww++) {
            sc += red[ww];
            sm += red[4 + ww];
            cn += reinterpret_cast<int*>(red)[8 + ww];
        }
        g_part_score[blk] = sc;
        g_part_msum[blk]  = sm;
        g_part_mcnt[blk]  = cn;
    }
}

// ============================================================
// Kernel 2: CRF forward recurrence (linear domain, lazy renorm)
//   measured-best R4 form: branchy steps, 128 blocks x 64 threads
// ============================================================
__global__ void __launch_bounds__(64)
crf_kernel(const float* __restrict__ trans, const float* __restrict__ start,
           const float* __restrict__ endt, const int* __restrict__ mask)
{
    const unsigned FULL = 0xffffffffu;
    int b = blockIdx.x * 2 + (threadIdx.x >> 5);
    int j = threadIdx.x & 31;
    bool act = (j < TT);

    float Ecol[TT];
    #pragma unroll
    for (int i = 0; i < TT; i++)
        Ecol[i] = act ? __expf(__ldg(trans + i * TT + j)) : 0.0f;
    float eend = act ? __expf(__ldg(endt + j)) : 0.0f;

    const float* eb = g_eem + (size_t)b * (SS * EST);
    const int4* mb = reinterpret_cast<const int4*>(mask + b * SS);

    float bufA[8], bufB[8];
    int   mA[8],  mB[8];

    #pragma unroll
    for (int d = 0; d < 8; d++)
        bufA[d] = act ? __ldg(eb + d * EST + j) : 0.0f;
    {
        int4 a = __ldg(mb + 0), c = __ldg(mb + 1);
        mA[0]=a.x; mA[1]=a.y; mA[2]=a.z; mA[3]=a.w;
        mA[4]=c.x; mA[5]=c.y; mA[6]=c.z; mA[7]=c.w;
    }

    float p = act ? bufA[0] * __expf(__ldg(start + j)) : 0.0f;
    float C = 0.0f;
    float r  = __shfl_sync(FULL, p, 0);
    float sc = __fdividef(1.0f, r);
    float lr = __logf(r);

    auto step = [&](float eemv, int mkv) {
        if (mkv != 0) {  // warp-uniform
            float a[4] = {0.f, 0.f, 0.f, 0.f};
            #pragma unroll
            for (int i = 0; i < TT; i++)
                a[i & 3] = fmaf(__shfl_sync(FULL, p, i), Ecol[i], a[i & 3]);
            float q = (a[0] + a[1]) + (a[2] + a[3]);
            p = q * (eemv * sc);
            C += lr;
            r  = __shfl_sync(FULL, p, 0);
            sc = __fdividef(1.0f, r);
            lr = __logf(r);
        }
    };

    #define PREFETCH(cidx, BUF, MARR)                                          \
        do {                                                                    \
            _Pragma("unroll")                                                   \
            for (int d = 0; d < 8; d++)                                         \
                BUF[d] = act ? __ldg(eb + ((cidx) * 8 + d) * EST + j) : 0.0f;   \
            int4 _a = __ldg(mb + 2 * (cidx)), _c = __ldg(mb + 2 * (cidx) + 1);  \
            MARR[0]=_a.x; MARR[1]=_a.y; MARR[2]=_a.z; MARR[3]=_a.w;             \
            MARR[4]=_c.x; MARR[5]=_c.y; MARR[6]=_c.z; MARR[7]=_c.w;             \
        } while (0)

    #define PROCESS(BUF, MARR)                                                  \
        do {                                                                    \
            _Pragma("unroll")                                                   \
            for (int d = 0; d < 8; d++) step(BUF[d], MARR[d]);                  \
        } while (0)

    PREFETCH(1, bufB, mB);
    #pragma unroll
    for (int d = 1; d < 8; d++) step(bufA[d], mA[d]);

    for (int cc = 1; cc < 63; cc += 2) {
        PREFETCH(cc + 1, bufA, mA);
        PROCESS(bufB, mB);
        PREFETCH(cc + 2, bufB, mB);
        PROCESS(bufA, mA);
    }
    PROCESS(bufB, mB);

    float term = p * eend;
    #pragma unroll
    for (int off = 16; off; off >>= 1)
        term += __shfl_xor_sync(FULL, term, off);
    if (j == 0) g_denom[b] = C + __logf(term);

    #undef PREFETCH
    #undef PROCESS
}

// ============================================================
// Kernel 3: finalize  out = -mean(score - denom)
// ============================================================
__global__ void __launch_bounds__(256)
fin_kernel(const int* __restrict__ labels, const float* __restrict__ endt,
           float* __restrict__ out)
{
    __shared__ float sred[256];
    int b = threadIdx.x;
    int cnt = 0;
    float psc = 0.0f, pms = 0.0f;
    #pragma unroll
    for (int k = 0; k < 4; k++) {
        cnt += g_part_mcnt[4 * b + k];
        psc += g_part_score[4 * b + k];
        pms += g_part_msum[4 * b + k];
    }
    int lt = __ldg(labels + b * SS + (cnt - 1));
    float score = psc + __ldg(endt + lt);
    float denom = g_denom[b] + pms;
    sred[b] = score - denom;
    __syncthreads();
    #pragma unroll
    for (int off = 128; off; off >>= 1) {
        if (b < off) sred[b] += sred[b + off];
        __syncthreads();
    }
    if (b == 0) out[0] = -sred[0] * (1.0f / BB);
}

// ============================================================
extern "C" void kernel_launch(void* const* d_in, const int* in_sizes, int n_in,
                              void* d_out, int out_size)
{
    const float* data   = (const float*)d_in[0];
    const int*   labels = (const int*)d_in[1];
    const int*   mask   = (const int*)d_in[2];
    const float* W      = (const float*)d_in[3];
    const float* bias   = (const float*)d_in[4];
    const float* start  = (const float*)d_in[5];
    const float* endt   = (const float*)d_in[6];
    const float* trans  = (const float*)d_in[7];

    cudaFuncSetAttribute(emis_kernel,
                         cudaFuncAttributeMaxDynamicSharedMemorySize, SM_TOT);

    emis_kernel<<<1024, 128, SM_TOT>>>(data, labels, mask, W, bias, start, trans);
    crf_kernel<<<BB / 2, 64>>>(trans, start, endt, mask);
    fin_kernel<<<1, 256>>>(labels, endt, (float*)d_out);
}

// round 11
// speedup vs baseline: 1.6867x; 1.1448x over previous
#include <cuda_runtime.h>
#include <cuda_bf16.h>
#include <cstdint>

#define BB 256
#define SS 512
#define DD 1024
#define TT 17
#define EST 20   // padded eem row stride (16B-aligned rows)

// ---------------- device scratch (no allocations allowed) ----------------
__device__ float g_eem[(size_t)BB * SS * EST];  // exp(em - rowmax), 10.5 MB
__device__ float g_part_score[1024];            // per-CTA numerator partials
__device__ float g_part_msum[1024];             // per-CTA sum of masked row-maxes
__device__ int   g_part_mcnt[1024];             // per-CTA mask counts
__device__ float g_denom[BB];                   // log partition minus msum offset

// ---------------- smem layout (bytes) ----------------
#define SM_B    0                       // W bf16: 24 n-rows x 1024 k = 48 KB
#define SM_A    49152                   // 4 warps x 1 buf x 4 KB = 16 KB
#define SM_D    SM_A                    // D reuse: 128 x 26 fp32 = 13312 B
#define SM_RED  (SM_A + 16384)          // 65536
#define SM_TOT  (SM_RED + 64)           // 65600

__device__ __forceinline__ uint2 cvt_f4_bf16x4(float4 f) {
    uint2 r;
    // low 16 bits = earlier k element
    asm("cvt.rn.bf16x2.f32 %0, %1, %2;" : "=r"(r.x) : "f"(f.y), "f"(f.x));
    asm("cvt.rn.bf16x2.f32 %0, %1, %2;" : "=r"(r.y) : "f"(f.w), "f"(f.z));
    return r;
}

__device__ __forceinline__ void mma16816(float* d, const uint32_t* a,
                                         const uint32_t* b) {
    asm volatile(
        "mma.sync.aligned.m16n8k16.row.col.f32.bf16.bf16.f32 "
        "{%0,%1,%2,%3}, {%4,%5,%6,%7}, {%8,%9}, {%0,%1,%2,%3};"
        : "+f"(d[0]), "+f"(d[1]), "+f"(d[2]), "+f"(d[3])
        : "r"(a[0]), "r"(a[1]), "r"(a[2]), "r"(a[3]), "r"(b[0]), "r"(b[1]));
}

// ============================================================
// Kernel 1: HMMA emissions GEMM + eem/rowmax + numerator partials
//   1024 CTAs x 128 threads, 3 CTAs/SM (12 warps) for DRAM latency cover.
// ============================================================
__global__ void __launch_bounds__(128, 3)
emis_kernel(const float* __restrict__ data, const int* __restrict__ labels,
            const int* __restrict__ mask, const float* __restrict__ W,
            const float* __restrict__ bias, const float* __restrict__ start,
            const float* __restrict__ trans)
{
    extern __shared__ char smem[];
    const int tid = threadIdx.x;
    const int blk = blockIdx.x;
    const int w   = tid >> 5;
    const int l   = tid & 31;

    // ---- stage B = W as bf16 [24 n x 1024 k], swizzled ----
    // zero rows 17..23: 7*2048 bytes = 896 uint4 (disjoint from W writes)
    for (int i = tid; i < 896; i += 128)
        reinterpret_cast<uint4*>(smem + SM_B + 17 * 2048)[i] =
            make_uint4(0u, 0u, 0u, 0u);
    // W rows 0..16, vectorized: float4 -> bf16x4 (8B, swizzle-contiguous)
    const float4* W4 = reinterpret_cast<const float4*>(W);
    for (int i = tid; i < TT * DD / 4; i += 128) {
        int n = i >> 8, k4 = i & 255;
        uint32_t off = (uint32_t)(n * 2048 + ((k4 * 8) ^ ((n & 7) << 4)));
        *reinterpret_cast<uint2*>(smem + SM_B + off) =
            cvt_f4_bf16x4(__ldg(W4 + i));
    }

    // ---- A staging geometry (warp-private, single 4 KB buffer) ----
    const int lr8 = l >> 4;                 // 0..1
    const int q   = l & 15;                 // float4 col within 64-float chunk
    const float4* dq = reinterpret_cast<const float4*>(data);
    const long g0 = (long)(blk * 128 + w * 32 + lr8) * 256 + q;  // float4 units
    char* buf = smem + SM_A + w * 4096;

    // prefetch chunk 0 RAW (no dependent ops -> all 16 LDGs in flight)
    float4 raw[16];
    #pragma unroll
    for (int i = 0; i < 16; i++)
        raw[i] = __ldg(dq + g0 + (long)i * 512);

    __syncthreads();   // B ready

    float acc[2][3][4];
    #pragma unroll
    for (int mt = 0; mt < 2; mt++)
        #pragma unroll
        for (int nt = 0; nt < 3; nt++)
            #pragma unroll
            for (int x = 0; x < 4; x++) acc[mt][nt][x] = 0.0f;

    const int rk = l >> 2;                   // fragment row & swizzle key
    const int cx = (l & 3) * 4;
    const uint32_t keysh = (uint32_t)rk << 4;
    char* sB = smem + SM_B;

    #pragma unroll 1
    for (int c = 0; c < 16; c++) {
        // CVT + STS of current chunk (consume raw regs)
        #pragma unroll
        for (int i = 0; i < 16; i++) {
            uint2 pk = cvt_f4_bf16x4(raw[i]);
            *reinterpret_cast<uint2*>(
                buf + (i * 2 + lr8) * 128 +
                ((q * 8) ^ (((i & 3) * 2 + lr8) << 4))) = pk;
        }
        __syncwarp();

        // prefetch next chunk RAW
        if (c < 15) {
            #pragma unroll
            for (int i = 0; i < 16; i++)
                raw[i] = __ldg(dq + g0 + (long)i * 512 + (c + 1) * 16);
        }

        // 4 ksteps of k=16
        #pragma unroll
        for (int ks = 0; ks < 4; ks++) {
            const uint32_t a0o = (uint32_t)(rk * 128) + (((uint32_t)(ks * 32 + cx)) ^ keysh);
            uint32_t aA[2][4];
            #pragma unroll
            for (int mt = 0; mt < 2; mt++) {
                char* bm = buf + mt * 2048;
                aA[mt][0] = *reinterpret_cast<uint32_t*>(bm + a0o);
                aA[mt][1] = *reinterpret_cast<uint32_t*>(bm + a0o + 1024);
                aA[mt][2] = *reinterpret_cast<uint32_t*>(bm + (a0o ^ 16));
                aA[mt][3] = *reinterpret_cast<uint32_t*>(bm + (a0o ^ 16) + 1024);
            }
            #pragma unroll
            for (int nt = 0; nt < 3; nt++) {
                const uint32_t b0o = (uint32_t)((nt * 8 + rk) * 2048) +
                    (((uint32_t)(c * 128 + ks * 32 + cx)) ^ keysh);
                uint32_t bb[2];
                bb[0] = *reinterpret_cast<uint32_t*>(sB + b0o);
                bb[1] = *reinterpret_cast<uint32_t*>(sB + (b0o ^ 16));
                mma16816(acc[0][nt], aA[0], bb);
                mma16816(acc[1][nt], aA[1], bb);
            }
        }
        __syncwarp();   // fragment reads done before next STS overwrites
    }

    // ---- D -> smem (stride 26 floats), then per-thread row epilogue ----
    __syncthreads();   // all warps done with A region
    float* sD = reinterpret_cast<float*>(smem + SM_D);
    #pragma unroll
    for (int mt = 0; mt < 2; mt++)
        #pragma unroll
        for (int nt = 0; nt < 3; nt++) {
            int r  = w * 32 + mt * 16 + rk;
            int cb = nt * 8 + (l & 3) * 2;
            *reinterpret_cast<float2*>(sD + r * 26 + cb) =
                make_float2(acc[mt][nt][0], acc[mt][nt][1]);
            *reinterpret_cast<float2*>(sD + (r + 8) * 26 + cb) =
                make_float2(acc[mt][nt][2], acc[mt][nt][3]);
        }
    __syncthreads();

    const int row = blk * 128 + tid;     // global row
    const int s   = row & (SS - 1);

    float emv[TT];
    float m = -1e30f;
    #pragma unroll
    for (int t = 0; t < TT; t++) {
        emv[t] = sD[tid * 26 + t] + __ldg(bias + t);
        m = fmaxf(m, emv[t]);
    }
    float e[TT];
    #pragma unroll
    for (int t = 0; t < TT; t++) e[t] = __expf(emv[t] - m);

    float4* o4 = reinterpret_cast<float4*>(g_eem + (size_t)row * EST);
    o4[0] = make_float4(e[0],  e[1],  e[2],  e[3]);
    o4[1] = make_float4(e[4],  e[5],  e[6],  e[7]);
    o4[2] = make_float4(e[8],  e[9],  e[10], e[11]);
    o4[3] = make_float4(e[12], e[13], e[14], e[15]);
    o4[4] = make_float4(e[16], 0.0f,  0.0f,  0.0f);

    int lab = __ldg(labels + row);
    float em_lab = 0.0f;
    #pragma unroll
    for (int t = 0; t < TT; t++) em_lab = (lab == t) ? emv[t] : em_lab;

    float mk = (__ldg(mask + row) != 0) ? 1.0f : 0.0f;
    float contrib;
    if (s == 0) {
        contrib = __ldg(start + lab) + em_lab;       // always included
    } else {
        int prev = __ldg(labels + row - 1);
        contrib = mk * (__ldg(trans + prev * TT + lab) + em_lab);
    }
    float msum_t = mk * m;
    int   mcnt_t = (mk > 0.0f) ? 1 : 0;

    // block reduction (deterministic)
    const unsigned FULL = 0xffffffffu;
    #pragma unroll
    for (int off = 16; off; off >>= 1) {
        contrib += __shfl_xor_sync(FULL, contrib, off);
        msum_t  += __shfl_xor_sync(FULL, msum_t, off);
        mcnt_t  += __shfl_xor_sync(FULL, mcnt_t, off);
    }
    float* red = reinterpret_cast<float*>(smem + SM_RED);
    if (l == 0) {
        red[w]     = contrib;
        red[4 + w] = msum_t;
        reinterpret_cast<int*>(red)[8 + w] = mcnt_t;
    }
    __syncthreads();
    if (tid == 0) {
        float sc = 0.0f, sm = 0.0f; int cn = 0;
        #pragma unroll
        for (int ww = 0; ww < 4; ww++) {
            sc += red[ww];
            sm += red[4 + ww];
            cn += reinterpret_cast<int*>(red)[8 + ww];
        }
        g_part_score[blk] = sc;
        g_part_msum[blk]  = sm;
        g_part_mcnt[blk]  = cn;
    }
}

// ============================================================
// Kernel 2: CRF forward recurrence (linear domain, lazy renorm)
//   measured-best R4 form: branchy steps, 128 blocks x 64 threads
// ============================================================
__global__ void __launch_bounds__(64)
crf_kernel(const float* __restrict__ trans, const float* __restrict__ start,
           const float* __restrict__ endt, const int* __restrict__ mask)
{
    const unsigned FULL = 0xffffffffu;
    int b = blockIdx.x * 2 + (threadIdx.x >> 5);
    int j = threadIdx.x & 31;
    bool act = (j < TT);

    float Ecol[TT];
    #pragma unroll
    for (int i = 0; i < TT; i++)
        Ecol[i] = act ? __expf(__ldg(trans + i * TT + j)) : 0.0f;
    float eend = act ? __expf(__ldg(endt + j)) : 0.0f;

    const float* eb = g_eem + (size_t)b * (SS * EST);
    const int4* mb = reinterpret_cast<const int4*>(mask + b * SS);

    float bufA[8], bufB[8];
    int   mA[8],  mB[8];

    #pragma unroll
    for (int d = 0; d < 8; d++)
        bufA[d] = act ? __ldg(eb + d * EST + j) : 0.0f;
    {
        int4 a = __ldg(mb + 0), c = __ldg(mb + 1);
        mA[0]=a.x; mA[1]=a.y; mA[2]=a.z; mA[3]=a.w;
        mA[4]=c.x; mA[5]=c.y; mA[6]=c.z; mA[7]=c.w;
    }

    float p = act ? bufA[0] * __expf(__ldg(start + j)) : 0.0f;
    float C = 0.0f;
    float r  = __shfl_sync(FULL, p, 0);
    float sc = __fdividef(1.0f, r);
    float lr = __logf(r);

    auto step = [&](float eemv, int mkv) {
        if (mkv != 0) {  // warp-uniform
            float a[4] = {0.f, 0.f, 0.f, 0.f};
            #pragma unroll
            for (int i = 0; i < TT; i++)
                a[i & 3] = fmaf(__shfl_sync(FULL, p, i), Ecol[i], a[i & 3]);
            float q = (a[0] + a[1]) + (a[2] + a[3]);
            p = q * (eemv * sc);
            C += lr;
            r  = __shfl_sync(FULL, p, 0);
            sc = __fdividef(1.0f, r);
            lr = __logf(r);
        }
    };

    #define PREFETCH(cidx, BUF, MARR)                                          \
        do {                                                                    \
            _Pragma("unroll")                                                   \
            for (int d = 0; d < 8; d++)                                         \
                BUF[d] = act ? __ldg(eb + ((cidx) * 8 + d) * EST + j) : 0.0f;   \
            int4 _a = __ldg(mb + 2 * (cidx)), _c = __ldg(mb + 2 * (cidx) + 1);  \
            MARR[0]=_a.x; MARR[1]=_a.y; MARR[2]=_a.z; MARR[3]=_a.w;             \
            MARR[4]=_c.x; MARR[5]=_c.y; MARR[6]=_c.z; MARR[7]=_c.w;             \
        } while (0)

    #define PROCESS(BUF, MARR)                                                  \
        do {                                                                    \
            _Pragma("unroll")                                                   \
            for (int d = 0; d < 8; d++) step(BUF[d], MARR[d]);                  \
        } while (0)

    PREFETCH(1, bufB, mB);
    #pragma unroll
    for (int d = 1; d < 8; d++) step(bufA[d], mA[d]);

    for (int cc = 1; cc < 63; cc += 2) {
        PREFETCH(cc + 1, bufA, mA);
        PROCESS(bufB, mB);
        PREFETCH(cc + 2, bufB, mB);
        PROCESS(bufA, mA);
    }
    PROCESS(bufB, mB);

    float term = p * eend;
    #pragma unroll
    for (int off = 16; off; off >>= 1)
        term += __shfl_xor_sync(FULL, term, off);
    if (j == 0) g_denom[b] = C + __logf(term);

    #undef PREFETCH
    #undef PROCESS
}

// ============================================================
// Kernel 3: finalize  out = -mean(score - denom)
// ============================================================
__global__ void __launch_bounds__(256)
fin_kernel(const int* __restrict__ labels, const float* __restrict__ endt,
           float* __restrict__ out)
{
    __shared__ float sred[256];
    int b = threadIdx.x;
    int cnt = 0;
    float psc = 0.0f, pms = 0.0f;
    #pragma unroll
    for (int k = 0; k < 4; k++) {
        cnt += g_part_mcnt[4 * b + k];
        psc += g_part_score[4 * b + k];
        pms += g_part_msum[4 * b + k];
    }
    int lt = __ldg(labels + b * SS + (cnt - 1));
    float score = psc + __ldg(endt + lt);
    float denom = g_denom[b] + pms;
    sred[b] = score - denom;
    __syncthreads();
    #pragma unroll
    for (int off = 128; off; off >>= 1) {
        if (b < off) sred[b] += sred[b + off];
        __syncthreads();
    }
    if (b == 0) out[0] = -sred[0] * (1.0f / BB);
}

// ============================================================
extern "C" void kernel_launch(void* const* d_in, const int* in_sizes, int n_in,
                              void* d_out, int out_size)
{
    const float* data   = (const float*)d_in[0];
    const int*   labels = (const int*)d_in[1];
    const int*   mask   = (const int*)d_in[2];
    const float* W      = (const float*)d_in[3];
    const float* bias   = (const float*)d_in[4];
    const float* start  = (const float*)d_in[5];
    const float* endt   = (const float*)d_in[6];
    const float* trans  = (const float*)d_in[7];

    cudaFuncSetAttribute(emis_kernel,
                         cudaFuncAttributeMaxDynamicSharedMemorySize, SM_TOT);

    emis_kernel<<<1024, 128, SM_TOT>>>(data, labels, mask, W, bias, start, trans);
    crf_kernel<<<BB / 2, 64>>>(trans, start, endt, mask);
    fin_kernel<<<1, 256>>>(labels, endt, (float*)d_out);
}